// round 16
// baseline (speedup 1.0000x reference)
#include <cuda_runtime.h>
#include <cuda_fp16.h>
#include <cstdint>
#include <math.h>

// Problem constants
#define BB   4
#define TT   4
#define CC   32
#define NN   16384
#define FF   64
#define KK   9
#define PADD 4

// Tiling
#define NT    128               // n per block
#define XS2   (NT + 2*PADD)     // 136 (u32 row stride of packed x; 136%32=8 -> conflict-free)
#define KDIM  (CC * KK)         // 288
#define NTHREADS 256

// SMEM layout (bytes)
#define SWB2_U2    (KK * 2 * 8 * 32)         // 4608 uint2 = 36864 B (fragment-ordered W)
#define SX2_WORDS  (16 * XS2)                // 2176 u32  =  8704 B (f16x2 x c-pairs)
#define SC_ELEMS   (3 * XS2)                 // 408 f32   =  1632 B
#define SDW2_WORDS (KK * NT)                 // 1152 u32  =  4608 B (duplicated f16x2 dw)
#define OFF_X2     (SWB2_U2 * 8)
#define OFF_C      (OFF_X2 + SX2_WORDS * 4)
#define OFF_DW     (OFF_C + SC_ELEMS * 4)
#define SMEM_BYTES (OFF_DW + SDW2_WORDS * 4) // 51808

__device__ __forceinline__ unsigned pack_f16x2(float lo, float hi) {
    unsigned r;
    asm("cvt.rn.f16x2.f32 %0, %1, %2;" : "=r"(r) : "f"(hi), "f"(lo));
    return r;
}
__device__ __forceinline__ unsigned hmul2u(unsigned a, unsigned b) {
    unsigned r;
    asm("mul.rn.f16x2 %0, %1, %2;" : "=r"(r) : "r"(a), "r"(b));
    return r;
}

#define MMA_F16_ACC(d, a0, a1, a2, a3, b0, b1)                                 \
    asm volatile("mma.sync.aligned.m16n8k16.row.col.f32.f16.f16.f32 "          \
                 "{%0,%1,%2,%3}, {%4,%5,%6,%7}, {%8,%9}, {%0,%1,%2,%3};"       \
                 : "+f"(d[0]), "+f"(d[1]), "+f"(d[2]), "+f"(d[3])              \
                 : "r"(a0), "r"(a1), "r"(a2), "r"(a3), "r"(b0), "r"(b1))

__device__ __forceinline__ float decode_sigma(const void* p) {
    const unsigned* w = (const unsigned*)p;
    unsigned lo = w[0];
    if (lo >= 1u && lo <= 1000000u) return (float)lo;          // int32/int64 low word
    float f = __uint_as_float(lo);
    if (f > 1e-6f && f < 1e6f) return f;                        // float32
    return (float)(*(const double*)p);                          // float64
}

__global__ __launch_bounds__(NTHREADS, 3)
void swconv1d_lean_kernel(const float* __restrict__ x,
                          const float* __restrict__ coords,
                          const float* __restrict__ weight,
                          const void*  __restrict__ sig,
                          float* __restrict__ out)
{
    extern __shared__ char smem_raw[];
    uint2*    s_wb2 = (uint2*)smem_raw;                  // [(k*2+h)*8+ft][lane] uint2
    unsigned* s_x2  = (unsigned*)(smem_raw + OFF_X2);    // [16][XS2] f16x2 c-pairs
    float*    s_c   = (float*)(smem_raw + OFF_C);        // [3][XS2]
    unsigned* s_dw2 = (unsigned*)(smem_raw + OFF_DW);    // [K][NT] f16x2(dw,dw)

    const int tid    = threadIdx.x;
    const int wid    = tid >> 5;                 // 0..7
    const int lane   = tid & 31;
    const int gid    = lane >> 2;                // groupID (0..7)
    const int tig    = lane & 3;                 // threadID_in_group (0..3)
    const int wsub   = wid & 3;                  // n strip (0..3)
    const int fhalf  = wid >> 2;                 // f half (0..1)
    const int bt     = blockIdx.y;
    const int t      = bt & 3;
    const int n_base = blockIdx.x * NT;

    const float inv_sigma = 1.0f / decode_sigma(sig);

    // ---- stage W[t] fragment-ordered: uint2 per (k, h, ft, lane) ----
    // lane' = gid'*4+tig'; f = ft*8+gid'; c base = 16h + 2tig'
    // .x = f16x2(W[f][c][k], W[f][c+1][k]);  .y = same at c+8
    {
        const float* wt = weight + (size_t)t * FF * KDIM;
        for (int i = tid; i < SWB2_U2; i += NTHREADS) {
            int lp  = i & 31;
            int ft  = (i >> 5) & 7;
            int s   = i >> 8;                    // 0..17 = k*2+h
            int k   = s >> 1;
            int h   = s & 1;
            int gg  = lp >> 2;
            int tg  = lp & 3;
            int f   = ft * 8 + gg;
            int cl  = h * 16 + 2 * tg;
            const float* wf = wt + (size_t)f * KDIM + k;   // wt[f*288 + c*9 + k]
            uint2 u;
            u.x = pack_f16x2(wf[(size_t)cl * KK],       wf[(size_t)(cl + 1) * KK]);
            u.y = pack_f16x2(wf[(size_t)(cl + 8) * KK], wf[(size_t)(cl + 9) * KK]);
            s_wb2[i] = u;
        }
    }
    // ---- stage x as f16x2 c-pairs: s_x2[c2][m] = (x[2c2][n], x[2c2+1][n]) ----
    {
        const float* xb = x + (size_t)bt * CC * NN;
        for (int i = tid; i < SX2_WORDS; i += NTHREADS) {
            int c2 = i / XS2;
            int m  = i - c2 * XS2;
            int n  = n_base + m - PADD;
            float lo = 0.0f, hi = 0.0f;
            if (n >= 0 && n < NN) {
                lo = xb[(size_t)(2 * c2) * NN + n];
                hi = xb[(size_t)(2 * c2 + 1) * NN + n];
            }
            s_x2[i] = pack_f16x2(lo, hi);
        }
    }
    // ---- stage coords tile (zero-padded) ----
    {
        const float* cb = coords + (size_t)bt * 3 * NN;
        for (int i = tid; i < SC_ELEMS; i += NTHREADS) {
            int c = i / XS2;
            int m = i - c * XS2;
            int n = n_base + m - PADD;
            s_c[i] = (n >= 0 && n < NN) ? cb[c * NN + n] : 0.0f;
        }
    }
    __syncthreads();

    // ---- distance weights as duplicated f16x2 ----
    for (int i = tid; i < KK * NT; i += NTHREADS) {
        int k = i >> 7;            // /128
        int j = i & (NT - 1);
        float d0 = s_c[0 * XS2 + j + k] - s_c[0 * XS2 + j + PADD];
        float d1 = s_c[1 * XS2 + j + k] - s_c[1 * XS2 + j + PADD];
        float d2 = s_c[2 * XS2 + j + k] - s_c[2 * XS2 + j + PADD];
        float dd = d0 * d0 + d1 * d1 + d2 * d2;
        float w  = 1.0f - sqrtf(dd) * inv_sigma;
        w = w > 0.0f ? w : 0.0f;
        s_dw2[i] = pack_f16x2(w, w);
    }
    __syncthreads();

    // ---- warp GEMM: 32 n (2 m16) x 32 f (4 n8) per warp ----
    const int n0 = wsub * 32 + gid;              // A/D base row

    float acc[2][4][4];
    #pragma unroll
    for (int mt = 0; mt < 2; ++mt)
        #pragma unroll
        for (int ft = 0; ft < 4; ++ft)
            #pragma unroll
            for (int r = 0; r < 4; ++r) acc[mt][ft][r] = 0.0f;

    const int fb4 = fhalf * 4;                   // this warp's ft offset in W frags

    #pragma unroll 1
    for (int k = 0; k < KK; ++k) {
        // duplicated-f16x2 dw at rows n0 + {0,8,16,24}
        unsigned dw2[4];
        #pragma unroll
        for (int r = 0; r < 4; ++r) dw2[r] = s_dw2[k * NT + n0 + 8 * r];

        const unsigned* xr = s_x2 + n0 + k;
        #pragma unroll
        for (int h = 0; h < 2; ++h) {
            const unsigned* pl = xr + (size_t)(h * 8 + tig) * XS2;    // c2 = 8h+tig
            const unsigned* ph = pl + 4 * XS2;                        // c2 = 8h+tig+4

            unsigned a[2][4];
            #pragma unroll
            for (int mt = 0; mt < 2; ++mt) {
                a[mt][0] = hmul2u(pl[16 * mt],     dw2[2 * mt]);
                a[mt][1] = hmul2u(pl[16 * mt + 8], dw2[2 * mt + 1]);
                a[mt][2] = hmul2u(ph[16 * mt],     dw2[2 * mt]);
                a[mt][3] = hmul2u(ph[16 * mt + 8], dw2[2 * mt + 1]);
            }

            #pragma unroll
            for (int ft = 0; ft < 4; ++ft) {
                uint2 b = s_wb2[(((k * 2 + h) * 8) + fb4 + ft) * 32 + lane];
                MMA_F16_ACC(acc[0][ft], a[0][0], a[0][1], a[0][2], a[0][3], b.x, b.y);
                MMA_F16_ACC(acc[1][ft], a[1][0], a[1][1], a[1][2], a[1][3], b.x, b.y);
            }
        }
    }

    // ---- epilogue: D row = n (gid/gid+8 [+16 for mt1]), col = f (2tig, 2tig+1) ----
    float* obase = out + (size_t)bt * FF * NN + n_base + n0;
    #pragma unroll
    for (int mt = 0; mt < 2; ++mt) {
        #pragma unroll
        for (int ft = 0; ft < 4; ++ft) {
            int f0 = fhalf * 32 + ft * 8 + 2 * tig;
            float* p = obase + mt * 16 + (size_t)f0 * NN;
            p[0]      = acc[mt][ft][0];   // (n,   f0)
            p[NN]     = acc[mt][ft][1];   // (n,   f0+1)
            p[8]      = acc[mt][ft][2];   // (n+8, f0)
            p[NN + 8] = acc[mt][ft][3];   // (n+8, f0+1)
        }
    }
}

extern "C" void kernel_launch(void* const* d_in, const int* in_sizes, int n_in,
                              void* d_out, int out_size)
{
    const float* x      = (const float*)d_in[0];
    const float* coords = (const float*)d_in[1];
    const float* weight = (const float*)d_in[2];
    const void*  sig    = d_in[3];
    float*       out    = (float*)d_out;

    cudaFuncSetAttribute(swconv1d_lean_kernel,
                         cudaFuncAttributeMaxDynamicSharedMemorySize, SMEM_BYTES);

    dim3 grid(NN / NT, BB * TT);   // (128, 16)
    swconv1d_lean_kernel<<<grid, NTHREADS, SMEM_BYTES>>>(x, coords, weight, sig, out);
}